// round 9
// baseline (speedup 1.0000x reference)
#include <cuda_runtime.h>
#include <cuda_bf16.h>

// ---------------------------------------------------------------------------
// Fused LEMURS actor, round 9:
//  - R8 structure (128-thr blocks, RPB=8, 8 blocks/SM, q in regs)
//  - attention exp is MUFU-bound (8cyc/exp-warp): offload 2 of every 8 exps
//    to the FMA pipe via packed-f32x2 polynomial 2^t (magic-add range split,
//    degree-4 Horner, exponent reinsert via shift-add) -> 6cyc/exp
//  - f32x2 t-computation and paired-FFMA2 num/den accumulation
//  - separate sk/sv arrays, 16B quad loads (warp-uniform broadcasts)
// ---------------------------------------------------------------------------

#define RPB 8
#define NTHREADS 128

typedef unsigned long long u64;

__device__ float g_WinT[12 * 128];
__device__ float g_AqT1[128 * 128];
__device__ float g_AkT1[128 * 128];
__device__ float g_AvT1[128 * 128];
__device__ float g_WhT[128 * 64];
__device__ float g_AqT2[64 * 64];
__device__ float g_AkT2[64 * 64];
__device__ float g_AvT2[64 * 64];

__device__ __forceinline__ u64 pack2(float a, float b) {
    u64 r;
    asm("mov.b64 %0, {%1, %2};" : "=l"(r) : "f"(a), "f"(b));
    return r;
}
__device__ __forceinline__ void ffma2(u64& d, u64 a, u64 b) {
    asm("fma.rn.f32x2 %0, %1, %2, %0;" : "+l"(d) : "l"(a), "l"(b));
}
__device__ __forceinline__ u64 fma2v(u64 a, u64 b, u64 c) {
    u64 d;
    asm("fma.rn.f32x2 %0, %1, %2, %3;" : "=l"(d) : "l"(a), "l"(b), "l"(c));
    return d;
}
__device__ __forceinline__ u64 mul2(u64 a, u64 b) {
    u64 d;
    asm("mul.rn.f32x2 %0, %1, %2;" : "=l"(d) : "l"(a), "l"(b));
    return d;
}
__device__ __forceinline__ u64 add2(u64 a, u64 b) {
    u64 d;
    asm("add.rn.f32x2 %0, %1, %2;" : "=l"(d) : "l"(a), "l"(b));
    return d;
}
__device__ __forceinline__ float2 unpack2(u64 v) {
    float2 f;
    asm("mov.b64 {%0, %1}, %2;" : "=f"(f.x), "=f"(f.y) : "l"(v));
    return f;
}
__device__ __forceinline__ float ex2f(float x) {
    float y;
    asm("ex2.approx.ftz.f32 %0, %1;" : "=f"(y) : "f"(x));
    return y;
}
__device__ __forceinline__ float siluf(float v) {
    return __fdividef(v, 1.0f + __expf(-v));
}

__global__ void prep_weights(const float* __restrict__ Win,
                             const float* __restrict__ Aq1,
                             const float* __restrict__ Ak1,
                             const float* __restrict__ Av1,
                             const float* __restrict__ Wh,
                             const float* __restrict__ Aq2,
                             const float* __restrict__ Ak2,
                             const float* __restrict__ Av2) {
    int t = blockIdx.x * blockDim.x + threadIdx.x;
    int stride = gridDim.x * blockDim.x;
    for (int idx = t; idx < 128 * 12; idx += stride) {
        int i = idx / 12, j = idx - i * 12;
        g_WinT[j * 128 + i] = Win[idx];
    }
    for (int idx = t; idx < 128 * 128; idx += stride) {
        int i = idx >> 7, j = idx & 127;
        g_AqT1[j * 128 + i] = Aq1[idx];
        g_AkT1[j * 128 + i] = Ak1[idx];
        g_AvT1[j * 128 + i] = Av1[idx];
    }
    for (int idx = t; idx < 64 * 128; idx += stride) {
        int i = idx >> 7, j = idx & 127;
        g_WhT[j * 64 + i] = Wh[idx];
    }
    for (int idx = t; idx < 64 * 64; idx += stride) {
        int i = idx >> 6, j = idx & 63;
        g_AqT2[j * 64 + i] = Aq2[idx];
        g_AkT2[j * 64 + i] = Ak2[idx];
        g_AvT2[j * 64 + i] = Av2[idx];
    }
}

#define HSTR 12

// One group of 8 exps: e0..e5 via MUFU, e6,e7 via f32x2 polynomial 2^t.
// qq = (q,q) packed; ka,kb = k0..k7; va,vb = v0..v7.
// Accumulates into na,nb (num) and da,db (den).
#define ATTN_G8(ka, kb, va, vb)                                              \
    {                                                                        \
        u64 t01 = mul2(qq, (ka).x);                                          \
        u64 t23 = mul2(qq, (ka).y);                                          \
        u64 t45 = mul2(qq, (kb).x);                                          \
        u64 t67 = mul2(qq, (kb).y);                                          \
        float2 f01 = unpack2(t01), f23 = unpack2(t23), f45 = unpack2(t45);   \
        float e0 = ex2f(f01.x), e1 = ex2f(f01.y);                            \
        float e2 = ex2f(f23.x), e3 = ex2f(f23.y);                            \
        float e4 = ex2f(f45.x), e5 = ex2f(f45.y);                            \
        u64 m  = add2(t67, MAGIC2);                                          \
        u64 nn = fma2v(MAGIC2, NONE2, m);      /* n = m - magic */           \
        u64 ff = fma2v(nn, NONE2, t67);        /* f = t - n     */           \
        u64 pp = fma2v(C4P, ff, C3P);                                        \
        pp = fma2v(pp, ff, C2P);                                             \
        pp = fma2v(pp, ff, C1P);                                             \
        pp = fma2v(pp, ff, ONE2);                                            \
        unsigned mlo = (unsigned)m, mhi = (unsigned)(m >> 32);               \
        float slo = __uint_as_float((mlo << 23) + 0x3F800000u);              \
        float shi = __uint_as_float((mhi << 23) + 0x3F800000u);              \
        u64 e67 = mul2(pp, pack2(slo, shi));                                 \
        u64 e01 = pack2(e0, e1), e23 = pack2(e2, e3), e45 = pack2(e4, e5);   \
        na = fma2v(e01, (va).x, na);                                         \
        nb = fma2v(e23, (va).y, nb);                                         \
        na = fma2v(e45, (vb).x, na);                                         \
        nb = fma2v(e67, (vb).y, nb);                                         \
        da = fma2v(e01, ONE2, da);                                           \
        db = fma2v(e23, ONE2, db);                                           \
        da = fma2v(e45, ONE2, da);                                           \
        db = fma2v(e67, ONE2, db);                                           \
    }

__global__ __launch_bounds__(NTHREADS, 8)
void lemurs_fused(const float* __restrict__ x,
                  const float* __restrict__ b_in,
                  const float* __restrict__ Bq1, const float* __restrict__ Bk1,
                  const float* __restrict__ Bv1,
                  const float* __restrict__ b_h,
                  const float* __restrict__ Bq2, const float* __restrict__ Bk2,
                  const float* __restrict__ Bv2,
                  const float* __restrict__ Wout,
                  const float* __restrict__ b_out,
                  float* __restrict__ out) {
    __shared__ __align__(16) float sx[RPB * 12];
    __shared__ __align__(16) float shT[128 * HSTR];   // h1 -> attn1out
    __shared__ __align__(16) float sk[RPB * 128];     // k1 / k2
    __shared__ __align__(16) float sv[RPB * 128];     // v1 / v2
    __shared__ __align__(16) float sh2T[64 * HSTR];   // h2
    __shared__ __align__(16) float sAt2[RPB * 64];    // attn2 out
    __shared__ float sy[RPB * 25];

    const int t = threadIdx.x;
    const int row0 = blockIdx.x * RPB;
    const float LOG2E = 1.4426950408889634f;

    if (t < RPB * 12) sx[t] = x[row0 * 12 + t];
    __syncthreads();

    const int i  = t;
    const int i2 = t & 63;
    const int g4 = t >> 6;

    // ---- phase 1: h1 = silu(x @ W_in^T + b_in) -> shT[feat*HSTR + row] ----
    {
        float acc[8];
        float bb = b_in[i];
#pragma unroll
        for (int r = 0; r < 8; r++) acc[r] = bb;
#pragma unroll
        for (int j = 0; j < 12; j++) {
            float w = g_WinT[j * 128 + i];
#pragma unroll
            for (int r = 0; r < 8; r++)
                acc[r] += w * sx[r * 12 + j];
        }
        float4 o0 = make_float4(siluf(acc[0]), siluf(acc[1]),
                                siluf(acc[2]), siluf(acc[3]));
        float4 o1 = make_float4(siluf(acc[4]), siluf(acc[5]),
                                siluf(acc[6]), siluf(acc[7]));
        *(float4*)&shT[i * HSTR]     = o0;
        *(float4*)&shT[i * HSTR + 4] = o1;
    }
    __syncthreads();

    // ---- phase 2: q1,k1,v1 (128x128 GEMMs, f32x2) ----
    float q[8];
    {
        u64 aq[4], ak[4], av[4];
        float bq = Bq1[i], bk = Bk1[i], bv = Bv1[i];
        u64 bq2 = pack2(bq, bq), bk2 = pack2(bk, bk), bv2 = pack2(bv, bv);
#pragma unroll
        for (int p = 0; p < 4; p++) { aq[p] = bq2; ak[p] = bk2; av[p] = bv2; }
#pragma unroll 4
        for (int j = 0; j < 128; j++) {
            float wq = g_AqT1[j * 128 + i];
            float wk = g_AkT1[j * 128 + i];
            float wv = g_AvT1[j * 128 + i];
            u64 wq2 = pack2(wq, wq), wk2 = pack2(wk, wk), wv2 = pack2(wv, wv);
            ulonglong2 ha = *(const ulonglong2*)&shT[j * HSTR];
            ulonglong2 hb = *(const ulonglong2*)&shT[j * HSTR + 4];
            ffma2(aq[0], wq2, ha.x); ffma2(aq[1], wq2, ha.y);
            ffma2(aq[2], wq2, hb.x); ffma2(aq[3], wq2, hb.y);
            ffma2(ak[0], wk2, ha.x); ffma2(ak[1], wk2, ha.y);
            ffma2(ak[2], wk2, hb.x); ffma2(ak[3], wk2, hb.y);
            ffma2(av[0], wv2, ha.x); ffma2(av[1], wv2, ha.y);
            ffma2(av[2], wv2, hb.x); ffma2(av[3], wv2, hb.y);
        }
#pragma unroll
        for (int p = 0; p < 4; p++) {
            float2 fq = unpack2(aq[p]);
            float2 fk = unpack2(ak[p]);
            float2 fv = unpack2(av[p]);
            int r0 = 2 * p;
            q[r0]     = siluf(fq.x) * LOG2E;
            q[r0 + 1] = siluf(fq.y) * LOG2E;
            sk[r0 * 128 + i]       = siluf(fk.x);
            sk[(r0 + 1) * 128 + i] = siluf(fk.y);
            sv[r0 * 128 + i]       = siluf(fv.x);
            sv[(r0 + 1) * 128 + i] = siluf(fv.y);
        }
    }
    __syncthreads();

    // packed constants for the poly-exp path (hoisted, live through phases 3&6)
    const u64 ONE2   = pack2(1.0f, 1.0f);
    const u64 NONE2  = pack2(-1.0f, -1.0f);
    const u64 MAGIC2 = pack2(12582912.0f, 12582912.0f);   // 1.5 * 2^23
    const u64 C4P = pack2(9.6181e-3f, 9.6181e-3f);
    const u64 C3P = pack2(5.5504109e-2f, 5.5504109e-2f);
    const u64 C2P = pack2(2.4022651e-1f, 2.4022651e-1f);
    const u64 C1P = pack2(6.9314718e-1f, 6.9314718e-1f);

    // ---- phase 3: attention 1 (hybrid MUFU/poly exp) ----
    {
#pragma unroll
        for (int r = 0; r < 8; r++) {
            const u64 qq = pack2(q[r], q[r]);
            const ulonglong2* kq = (const ulonglong2*)&sk[r * 128];
            const ulonglong2* vq = (const ulonglong2*)&sv[r * 128];
            u64 na = 0, nb = 0, da = 0, db = 0;
#pragma unroll 2
            for (int gI = 0; gI < 16; gI++) {
                ulonglong2 ka = kq[2 * gI], kb = kq[2 * gI + 1];
                ulonglong2 va = vq[2 * gI], vb = vq[2 * gI + 1];
                ATTN_G8(ka, kb, va, vb);
            }
            float2 A = unpack2(na), B = unpack2(nb);
            float2 C = unpack2(da), D = unpack2(db);
            float num = (A.x + A.y) + (B.x + B.y);
            float den = (C.x + C.y) + (D.x + D.y);
            shT[i * HSTR + r] = siluf(__fdividef(num, den));
        }
    }
    __syncthreads();

    // ---- phase 4: h2 = silu(attn1 @ W_h^T + b_h) -> sh2T ----
    {
        u64 a2[2];
        float bb = b_h[i2];
        a2[0] = a2[1] = pack2(bb, bb);
#pragma unroll 4
        for (int j = 0; j < 128; j++) {
            float w = g_WhT[j * 64 + i2];
            u64 w2 = pack2(w, w);
            ulonglong2 hv = *(const ulonglong2*)&shT[j * HSTR + g4 * 4];
            ffma2(a2[0], w2, hv.x);
            ffma2(a2[1], w2, hv.y);
        }
        float2 f0 = unpack2(a2[0]), f1 = unpack2(a2[1]);
        float4 o = make_float4(siluf(f0.x), siluf(f0.y),
                               siluf(f1.x), siluf(f1.y));
        *(float4*)&sh2T[i2 * HSTR + g4 * 4] = o;
    }
    __syncthreads();

    // ---- phase 5: q2,k2,v2 (64x64 GEMMs) ----
    float q2r[4];
    {
        u64 aq[2], ak[2], av[2];
        float bq = Bq2[i2], bk = Bk2[i2], bv = Bv2[i2];
        aq[0] = aq[1] = pack2(bq, bq);
        ak[0] = ak[1] = pack2(bk, bk);
        av[0] = av[1] = pack2(bv, bv);
#pragma unroll 4
        for (int j = 0; j < 64; j++) {
            float wq = g_AqT2[j * 64 + i2];
            float wk = g_AkT2[j * 64 + i2];
            float wv = g_AvT2[j * 64 + i2];
            u64 wq2 = pack2(wq, wq), wk2 = pack2(wk, wk), wv2 = pack2(wv, wv);
            ulonglong2 hv = *(const ulonglong2*)&sh2T[j * HSTR + g4 * 4];
            ffma2(aq[0], wq2, hv.x); ffma2(aq[1], wq2, hv.y);
            ffma2(ak[0], wk2, hv.x); ffma2(ak[1], wk2, hv.y);
            ffma2(av[0], wv2, hv.x); ffma2(av[1], wv2, hv.y);
        }
#pragma unroll
        for (int p = 0; p < 2; p++) {
            float2 fq = unpack2(aq[p]);
            float2 fk = unpack2(ak[p]);
            float2 fv = unpack2(av[p]);
            int r0 = g4 * 4 + 2 * p;
            q2r[2 * p]     = siluf(fq.x) * LOG2E;
            q2r[2 * p + 1] = siluf(fq.y) * LOG2E;
            sk[r0 * 64 + i2]       = siluf(fk.x);
            sk[(r0 + 1) * 64 + i2] = siluf(fk.y);
            sv[r0 * 64 + i2]       = siluf(fv.x);
            sv[(r0 + 1) * 64 + i2] = siluf(fv.y);
        }
    }
    __syncthreads();

    // ---- phase 6: attention 2 (hybrid) ----
    {
#pragma unroll
        for (int r = 0; r < 4; r++) {
            int row = g4 * 4 + r;
            const u64 qq = pack2(q2r[r], q2r[r]);
            const ulonglong2* kq = (const ulonglong2*)&sk[row * 64];
            const ulonglong2* vq = (const ulonglong2*)&sv[row * 64];
            u64 na = 0, nb = 0, da = 0, db = 0;
#pragma unroll 2
            for (int gI = 0; gI < 8; gI++) {
                ulonglong2 ka = kq[2 * gI], kb = kq[2 * gI + 1];
                ulonglong2 va = vq[2 * gI], vb = vq[2 * gI + 1];
                ATTN_G8(ka, kb, va, vb);
            }
            float2 A = unpack2(na), B = unpack2(nb);
            float2 C = unpack2(da), D = unpack2(db);
            float num = (A.x + A.y) + (B.x + B.y);
            float den = (C.x + C.y) + (D.x + D.y);
            sAt2[row * 64 + i2] = siluf(__fdividef(num, den));
        }
    }
    __syncthreads();

    // ---- phase 7: y = silu(attn2 @ W_out^T + b_out) ----
    for (int idx = t; idx < RPB * 25; idx += NTHREADS) {
        int r = idx / 25;
        int o = idx - r * 25;
        float acc = b_out[o];
        const float4* wrow = (const float4*)&Wout[o * 64];
        const float4* arow = (const float4*)&sAt2[r * 64];
#pragma unroll
        for (int j = 0; j < 16; j++) {
            float4 w = wrow[j];
            float4 a = arow[j];
            acc += w.x * a.x + w.y * a.y + w.z * a.z + w.w * a.w;
        }
        sy[idx] = siluf(acc);
    }
    __syncthreads();

    // ---- phase 8: quadratic-form reduction ----
    if (t < RPB) {
        const float* y = &sy[t * 25];
        float M11 = 0.f, M12 = 0.f, M21 = 0.f, M22 = 0.f, Mpp = 0.f;
#pragma unroll
        for (int j = 0; j < 5; j++) {
            M11 += y[j] * y[j];
            M12 += y[5 + j] * y[5 + j];
            M21 += y[10 + j] * y[10 + j];
            M22 += y[15 + j] * y[15 + j];
            Mpp += y[20 + j] * y[20 + j];
        }
        float q0 = y[0], q1 = y[1], qq2 = y[2], q3 = y[3];
        float quad = M11 * (q0 * q0 + q1 * q1)
                   + (M12 + M21) * (q0 * qq2 + q1 * q3)
                   + M22 * (qq2 * qq2 + q3 * q3);
        out[row0 + t] = quad + Mpp;
    }
}

extern "C" void kernel_launch(void* const* d_in, const int* in_sizes, int n_in,
                              void* d_out, int out_size) {
    const float* x     = (const float*)d_in[0];
    const float* W_in  = (const float*)d_in[2];
    const float* b_in  = (const float*)d_in[3];
    const float* Aq4   = (const float*)d_in[4];
    const float* Bq4   = (const float*)d_in[5];
    const float* Ak4   = (const float*)d_in[6];
    const float* Bk4   = (const float*)d_in[7];
    const float* Av4   = (const float*)d_in[8];
    const float* Bv4   = (const float*)d_in[9];
    const float* W_h   = (const float*)d_in[10];
    const float* b_h   = (const float*)d_in[11];
    const float* Aq7   = (const float*)d_in[12];
    const float* Bq7   = (const float*)d_in[13];
    const float* Ak7   = (const float*)d_in[14];
    const float* Bk7   = (const float*)d_in[15];
    const float* Av7   = (const float*)d_in[16];
    const float* Bv7   = (const float*)d_in[17];
    const float* W_out = (const float*)d_in[18];
    const float* b_out = (const float*)d_in[19];

    int nrows = in_sizes[0] / 12;

    prep_weights<<<64, 256>>>(W_in, Aq4, Ak4, Av4, W_h, Aq7, Ak7, Av7);
    lemurs_fused<<<nrows / RPB, NTHREADS>>>(x, b_in, Bq4, Bk4, Bv4,
                                            b_h, Bq7, Bk7, Bv7,
                                            W_out, b_out, (float*)d_out);
}

// round 11
// speedup vs baseline: 1.0013x; 1.0013x over previous
#include <cuda_runtime.h>
#include <cuda_bf16.h>

// ---------------------------------------------------------------------------
// Fused LEMURS actor, round 10:
//  - all-MUFU attention at 3.5 instr/exp (f32x2 t-compute + paired-FFMA2
//    accumulation, NO poly path -> ALU pipe freed)
//  - persistent work-stealing grid: 1184 blocks (148 SM x 8), tiles pulled
//    from a global atomic counter -> no 73%-full second wave
//  - otherwise R8/R9 structure: 128-thr blocks, RPB=8 tiles, q in regs
// ---------------------------------------------------------------------------

#define RPB 8
#define NTHREADS 128
#define NBLOCKS (148 * 8)

typedef unsigned long long u64;

__device__ float g_WinT[12 * 128];
__device__ float g_AqT1[128 * 128];
__device__ float g_AkT1[128 * 128];
__device__ float g_AvT1[128 * 128];
__device__ float g_WhT[128 * 64];
__device__ float g_AqT2[64 * 64];
__device__ float g_AkT2[64 * 64];
__device__ float g_AvT2[64 * 64];
__device__ unsigned g_tile_ctr;

__device__ __forceinline__ u64 pack2(float a, float b) {
    u64 r;
    asm("mov.b64 %0, {%1, %2};" : "=l"(r) : "f"(a), "f"(b));
    return r;
}
__device__ __forceinline__ void ffma2(u64& d, u64 a, u64 b) {
    asm("fma.rn.f32x2 %0, %1, %2, %0;" : "+l"(d) : "l"(a), "l"(b));
}
__device__ __forceinline__ u64 fma2v(u64 a, u64 b, u64 c) {
    u64 d;
    asm("fma.rn.f32x2 %0, %1, %2, %3;" : "=l"(d) : "l"(a), "l"(b), "l"(c));
    return d;
}
__device__ __forceinline__ u64 mul2(u64 a, u64 b) {
    u64 d;
    asm("mul.rn.f32x2 %0, %1, %2;" : "=l"(d) : "l"(a), "l"(b));
    return d;
}
__device__ __forceinline__ float2 unpack2(u64 v) {
    float2 f;
    asm("mov.b64 {%0, %1}, %2;" : "=f"(f.x), "=f"(f.y) : "l"(v));
    return f;
}
__device__ __forceinline__ float ex2f(float x) {
    float y;
    asm("ex2.approx.ftz.f32 %0, %1;" : "=f"(y) : "f"(x));
    return y;
}
__device__ __forceinline__ float siluf(float v) {
    return __fdividef(v, 1.0f + __expf(-v));
}

__global__ void prep_weights(const float* __restrict__ Win,
                             const float* __restrict__ Aq1,
                             const float* __restrict__ Ak1,
                             const float* __restrict__ Av1,
                             const float* __restrict__ Wh,
                             const float* __restrict__ Aq2,
                             const float* __restrict__ Ak2,
                             const float* __restrict__ Av2) {
    int t = blockIdx.x * blockDim.x + threadIdx.x;
    if (t == 0) g_tile_ctr = 0;   // reset work-steal counter (runs before main kernel)
    int stride = gridDim.x * blockDim.x;
    for (int idx = t; idx < 128 * 12; idx += stride) {
        int i = idx / 12, j = idx - i * 12;
        g_WinT[j * 128 + i] = Win[idx];
    }
    for (int idx = t; idx < 128 * 128; idx += stride) {
        int i = idx >> 7, j = idx & 127;
        g_AqT1[j * 128 + i] = Aq1[idx];
        g_AkT1[j * 128 + i] = Ak1[idx];
        g_AvT1[j * 128 + i] = Av1[idx];
    }
    for (int idx = t; idx < 64 * 128; idx += stride) {
        int i = idx >> 7, j = idx & 127;
        g_WhT[j * 64 + i] = Wh[idx];
    }
    for (int idx = t; idx < 64 * 64; idx += stride) {
        int i = idx >> 6, j = idx & 63;
        g_AqT2[j * 64 + i] = Aq2[idx];
        g_AkT2[j * 64 + i] = Ak2[idx];
        g_AvT2[j * 64 + i] = Av2[idx];
    }
}

#define HSTR 12

// 8 exps, all MUFU: f32x2 t-compute, paired-FFMA2 accumulation.
// 28 instrs / 8 exps = 3.5 instr/exp.
#define ATTN_G8(ka, kb, va, vb)                                              \
    {                                                                        \
        u64 t01 = mul2(qq, (ka).x);                                          \
        u64 t23 = mul2(qq, (ka).y);                                          \
        u64 t45 = mul2(qq, (kb).x);                                          \
        u64 t67 = mul2(qq, (kb).y);                                          \
        float2 f01 = unpack2(t01), f23 = unpack2(t23);                       \
        float2 f45 = unpack2(t45), f67 = unpack2(t67);                       \
        u64 e01 = pack2(ex2f(f01.x), ex2f(f01.y));                           \
        u64 e23 = pack2(ex2f(f23.x), ex2f(f23.y));                           \
        u64 e45 = pack2(ex2f(f45.x), ex2f(f45.y));                           \
        u64 e67 = pack2(ex2f(f67.x), ex2f(f67.y));                           \
        na = fma2v(e01, (va).x, na);                                         \
        nb = fma2v(e23, (va).y, nb);                                         \
        na = fma2v(e45, (vb).x, na);                                         \
        nb = fma2v(e67, (vb).y, nb);                                         \
        da = fma2v(e01, ONE2, da);                                           \
        db = fma2v(e23, ONE2, db);                                           \
        da = fma2v(e45, ONE2, da);                                           \
        db = fma2v(e67, ONE2, db);                                           \
    }

__global__ __launch_bounds__(NTHREADS, 8)
void lemurs_fused(const float* __restrict__ x,
                  const float* __restrict__ b_in,
                  const float* __restrict__ Bq1, const float* __restrict__ Bk1,
                  const float* __restrict__ Bv1,
                  const float* __restrict__ b_h,
                  const float* __restrict__ Bq2, const float* __restrict__ Bk2,
                  const float* __restrict__ Bv2,
                  const float* __restrict__ Wout,
                  const float* __restrict__ b_out,
                  float* __restrict__ out,
                  int ntiles) {
    __shared__ __align__(16) float sx[RPB * 12];
    __shared__ __align__(16) float shT[128 * HSTR];   // h1 -> attn1out
    __shared__ __align__(16) float sk[RPB * 128];     // k1 / k2
    __shared__ __align__(16) float sv[RPB * 128];     // v1 / v2
    __shared__ __align__(16) float sh2T[64 * HSTR];   // h2
    __shared__ __align__(16) float sAt2[RPB * 64];    // attn2 out
    __shared__ float sy[RPB * 25];
    __shared__ unsigned s_tile;

    const int t = threadIdx.x;
    const float LOG2E = 1.4426950408889634f;
    const u64 ONE2 = pack2(1.0f, 1.0f);

    const int i  = t;
    const int i2 = t & 63;
    const int g4 = t >> 6;

    for (;;) {
        if (t == 0) s_tile = atomicAdd(&g_tile_ctr, 1u);
        __syncthreads();
        const unsigned tile = s_tile;
        if (tile >= (unsigned)ntiles) return;
        const int row0 = tile * RPB;

        if (t < RPB * 12) sx[t] = x[row0 * 12 + t];
        __syncthreads();

        // ---- phase 1: h1 = silu(x @ W_in^T + b_in) ----
        {
            float acc[8];
            float bb = b_in[i];
#pragma unroll
            for (int r = 0; r < 8; r++) acc[r] = bb;
#pragma unroll
            for (int j = 0; j < 12; j++) {
                float w = g_WinT[j * 128 + i];
#pragma unroll
                for (int r = 0; r < 8; r++)
                    acc[r] += w * sx[r * 12 + j];
            }
            float4 o0 = make_float4(siluf(acc[0]), siluf(acc[1]),
                                    siluf(acc[2]), siluf(acc[3]));
            float4 o1 = make_float4(siluf(acc[4]), siluf(acc[5]),
                                    siluf(acc[6]), siluf(acc[7]));
            *(float4*)&shT[i * HSTR]     = o0;
            *(float4*)&shT[i * HSTR + 4] = o1;
        }
        __syncthreads();

        // ---- phase 2: q1,k1,v1 (128x128 GEMMs, f32x2) ----
        float q[8];
        {
            u64 aq[4], ak[4], av[4];
            float bq = Bq1[i], bk = Bk1[i], bv = Bv1[i];
            u64 bq2 = pack2(bq, bq), bk2 = pack2(bk, bk), bv2 = pack2(bv, bv);
#pragma unroll
            for (int p = 0; p < 4; p++) { aq[p] = bq2; ak[p] = bk2; av[p] = bv2; }
#pragma unroll 4
            for (int j = 0; j < 128; j++) {
                float wq = g_AqT1[j * 128 + i];
                float wk = g_AkT1[j * 128 + i];
                float wv = g_AvT1[j * 128 + i];
                u64 wq2 = pack2(wq, wq), wk2 = pack2(wk, wk), wv2 = pack2(wv, wv);
                ulonglong2 ha = *(const ulonglong2*)&shT[j * HSTR];
                ulonglong2 hb = *(const ulonglong2*)&shT[j * HSTR + 4];
                ffma2(aq[0], wq2, ha.x); ffma2(aq[1], wq2, ha.y);
                ffma2(aq[2], wq2, hb.x); ffma2(aq[3], wq2, hb.y);
                ffma2(ak[0], wk2, ha.x); ffma2(ak[1], wk2, ha.y);
                ffma2(ak[2], wk2, hb.x); ffma2(ak[3], wk2, hb.y);
                ffma2(av[0], wv2, ha.x); ffma2(av[1], wv2, ha.y);
                ffma2(av[2], wv2, hb.x); ffma2(av[3], wv2, hb.y);
            }
#pragma unroll
            for (int p = 0; p < 4; p++) {
                float2 fq = unpack2(aq[p]);
                float2 fk = unpack2(ak[p]);
                float2 fv = unpack2(av[p]);
                int r0 = 2 * p;
                q[r0]     = siluf(fq.x) * LOG2E;
                q[r0 + 1] = siluf(fq.y) * LOG2E;
                sk[r0 * 128 + i]       = siluf(fk.x);
                sk[(r0 + 1) * 128 + i] = siluf(fk.y);
                sv[r0 * 128 + i]       = siluf(fv.x);
                sv[(r0 + 1) * 128 + i] = siluf(fv.y);
            }
        }
        __syncthreads();

        // ---- phase 3: attention 1 (all-MUFU, 3.5 instr/exp) ----
        {
#pragma unroll
            for (int r = 0; r < 8; r++) {
                const u64 qq = pack2(q[r], q[r]);
                const ulonglong2* kq = (const ulonglong2*)&sk[r * 128];
                const ulonglong2* vq = (const ulonglong2*)&sv[r * 128];
                u64 na = 0, nb = 0, da = 0, db = 0;
#pragma unroll 4
                for (int gI = 0; gI < 16; gI++) {
                    ulonglong2 ka = kq[2 * gI], kb = kq[2 * gI + 1];
                    ulonglong2 va = vq[2 * gI], vb = vq[2 * gI + 1];
                    ATTN_G8(ka, kb, va, vb);
                }
                float2 A = unpack2(na), B = unpack2(nb);
                float2 C = unpack2(da), D = unpack2(db);
                float num = (A.x + A.y) + (B.x + B.y);
                float den = (C.x + C.y) + (D.x + D.y);
                shT[i * HSTR + r] = siluf(__fdividef(num, den));
            }
        }
        __syncthreads();

        // ---- phase 4: h2 = silu(attn1 @ W_h^T + b_h) ----
        {
            u64 a2[2];
            float bb = b_h[i2];
            a2[0] = a2[1] = pack2(bb, bb);
#pragma unroll 4
            for (int j = 0; j < 128; j++) {
                float w = g_WhT[j * 64 + i2];
                u64 w2 = pack2(w, w);
                ulonglong2 hv = *(const ulonglong2*)&shT[j * HSTR + g4 * 4];
                ffma2(a2[0], w2, hv.x);
                ffma2(a2[1], w2, hv.y);
            }
            float2 f0 = unpack2(a2[0]), f1 = unpack2(a2[1]);
            float4 o = make_float4(siluf(f0.x), siluf(f0.y),
                                   siluf(f1.x), siluf(f1.y));
            *(float4*)&sh2T[i2 * HSTR + g4 * 4] = o;
        }
        __syncthreads();

        // ---- phase 5: q2,k2,v2 (64x64 GEMMs) ----
        float q2r[4];
        {
            u64 aq[2], ak[2], av[2];
            float bq = Bq2[i2], bk = Bk2[i2], bv = Bv2[i2];
            aq[0] = aq[1] = pack2(bq, bq);
            ak[0] = ak[1] = pack2(bk, bk);
            av[0] = av[1] = pack2(bv, bv);
#pragma unroll 4
            for (int j = 0; j < 64; j++) {
                float wq = g_AqT2[j * 64 + i2];
                float wk = g_AkT2[j * 64 + i2];
                float wv = g_AvT2[j * 64 + i2];
                u64 wq2 = pack2(wq, wq), wk2 = pack2(wk, wk), wv2 = pack2(wv, wv);
                ulonglong2 hv = *(const ulonglong2*)&sh2T[j * HSTR + g4 * 4];
                ffma2(aq[0], wq2, hv.x); ffma2(aq[1], wq2, hv.y);
                ffma2(ak[0], wk2, hv.x); ffma2(ak[1], wk2, hv.y);
                ffma2(av[0], wv2, hv.x); ffma2(av[1], wv2, hv.y);
            }
#pragma unroll
            for (int p = 0; p < 2; p++) {
                float2 fq = unpack2(aq[p]);
                float2 fk = unpack2(ak[p]);
                float2 fv = unpack2(av[p]);
                int r0 = g4 * 4 + 2 * p;
                q2r[2 * p]     = siluf(fq.x) * LOG2E;
                q2r[2 * p + 1] = siluf(fq.y) * LOG2E;
                sk[r0 * 64 + i2]       = siluf(fk.x);
                sk[(r0 + 1) * 64 + i2] = siluf(fk.y);
                sv[r0 * 64 + i2]       = siluf(fv.x);
                sv[(r0 + 1) * 64 + i2] = siluf(fv.y);
            }
        }
        __syncthreads();

        // ---- phase 6: attention 2 (all-MUFU) ----
        {
#pragma unroll
            for (int r = 0; r < 4; r++) {
                int row = g4 * 4 + r;
                const u64 qq = pack2(q2r[r], q2r[r]);
                const ulonglong2* kq = (const ulonglong2*)&sk[row * 64];
                const ulonglong2* vq = (const ulonglong2*)&sv[row * 64];
                u64 na = 0, nb = 0, da = 0, db = 0;
#pragma unroll 4
                for (int gI = 0; gI < 8; gI++) {
                    ulonglong2 ka = kq[2 * gI], kb = kq[2 * gI + 1];
                    ulonglong2 va = vq[2 * gI], vb = vq[2 * gI + 1];
                    ATTN_G8(ka, kb, va, vb);
                }
                float2 A = unpack2(na), B = unpack2(nb);
                float2 C = unpack2(da), D = unpack2(db);
                float num = (A.x + A.y) + (B.x + B.y);
                float den = (C.x + C.y) + (D.x + D.y);
                sAt2[row * 64 + i2] = siluf(__fdividef(num, den));
            }
        }
        __syncthreads();

        // ---- phase 7: y = silu(attn2 @ W_out^T + b_out) ----
        for (int idx = t; idx < RPB * 25; idx += NTHREADS) {
            int r = idx / 25;
            int o = idx - r * 25;
            float acc = b_out[o];
            const float4* wrow = (const float4*)&Wout[o * 64];
            const float4* arow = (const float4*)&sAt2[r * 64];
#pragma unroll
            for (int j = 0; j < 16; j++) {
                float4 w = wrow[j];
                float4 a = arow[j];
                acc += w.x * a.x + w.y * a.y + w.z * a.z + w.w * a.w;
            }
            sy[idx] = siluf(acc);
        }
        __syncthreads();

        // ---- phase 8: quadratic-form reduction ----
        if (t < RPB) {
            const float* y = &sy[t * 25];
            float M11 = 0.f, M12 = 0.f, M21 = 0.f, M22 = 0.f, Mpp = 0.f;
#pragma unroll
            for (int j = 0; j < 5; j++) {
                M11 += y[j] * y[j];
                M12 += y[5 + j] * y[5 + j];
                M21 += y[10 + j] * y[10 + j];
                M22 += y[15 + j] * y[15 + j];
                Mpp += y[20 + j] * y[20 + j];
            }
            float q0 = y[0], q1 = y[1], qq2 = y[2], q3 = y[3];
            float quad = M11 * (q0 * q0 + q1 * q1)
                       + (M12 + M21) * (q0 * qq2 + q1 * q3)
                       + M22 * (qq2 * qq2 + q3 * q3);
            out[row0 + t] = quad + Mpp;
        }
        __syncthreads();   // protect sy/smem + s_tile before next iteration
    }
}

extern "C" void kernel_launch(void* const* d_in, const int* in_sizes, int n_in,
                              void* d_out, int out_size) {
    const float* x     = (const float*)d_in[0];
    const float* W_in  = (const float*)d_in[2];
    const float* b_in  = (const float*)d_in[3];
    const float* Aq4   = (const float*)d_in[4];
    const float* Bq4   = (const float*)d_in[5];
    const float* Ak4   = (const float*)d_in[6];
    const float* Bk4   = (const float*)d_in[7];
    const float* Av4   = (const float*)d_in[8];
    const float* Bv4   = (const float*)d_in[9];
    const float* W_h   = (const float*)d_in[10];
    const float* b_h   = (const float*)d_in[11];
    const float* Aq7   = (const float*)d_in[12];
    const float* Bq7   = (const float*)d_in[13];
    const float* Ak7   = (const float*)d_in[14];
    const float* Bk7   = (const float*)d_in[15];
    const float* Av7   = (const float*)d_in[16];
    const float* Bv7   = (const float*)d_in[17];
    const float* W_out = (const float*)d_in[18];
    const float* b_out = (const float*)d_in[19];

    int nrows = in_sizes[0] / 12;
    int ntiles = nrows / RPB;
    int nblocks = NBLOCKS < ntiles ? NBLOCKS : ntiles;

    prep_weights<<<64, 256>>>(W_in, Aq4, Ak4, Av4, W_h, Aq7, Ak7, Av7);
    lemurs_fused<<<nblocks, NTHREADS>>>(x, b_in, Bq4, Bk4, Bv4,
                                        b_h, Bq7, Bk7, Bv7,
                                        W_out, b_out, (float*)d_out, ntiles);
}